// round 12
// baseline (speedup 1.0000x reference)
#include <cuda_runtime.h>
#include <cuda_fp16.h>
#include <cstdint>

#define NB   8
#define CC   256
#define HW   4096
#define MALL 320   // 32 Q rows + 32 K rows + 256 U rows

#define USCALE    4096.0f          // 2^12, lifts U''/z out of fp16 subnormal range
#define UNSCALE   (1.0f / 4096.0f)

// ---------------- device scratch ----------------
__device__ __align__(128) float g_WallT[CC * MALL];                 // [c][m]
__device__ __align__(128) float g_QKU[(size_t)NB * MALL * HW];      // [n][m][l]
__device__ __align__(128) float g_Z[(size_t)NB * HW];               // row sums z_i
__device__ __align__(128) __half g_Uh[(size_t)NB * CC * HW];        // U''·2^12 [n][o][i]
__device__ __align__(128) __half g_Ph[(size_t)NB * HW * HW];        // P^T [n][j][i] fp16

// ---------------- K0: build combined weight matrix (transposed) + zero g_Z ----------------
__global__ void build_wall(const float* __restrict__ Wq, const float* __restrict__ Wk,
                           const float* __restrict__ Wv, const float* __restrict__ Wo,
                           const float* __restrict__ gammap) {
    int m = blockIdx.x;      // 0..319
    int c = threadIdx.x;     // 0..255
    int idx = m * 256 + c;
    if (idx < NB * HW) g_Z[idx] = 0.f;    // folded memset
    float v;
    if (m < 32) {
        v = Wq[m * CC + c];
    } else if (m < 64) {
        v = Wk[(m - 32) * CC + c];
    } else {
        int o = m - 64;
        float acc = 0.f;
        for (int t = 0; t < CC; ++t)
            acc = fmaf(Wo[o * CC + t], Wv[t * CC + c], acc);
        v = acc * gammap[0];
    }
    g_WallT[c * MALL + m] = v;
}

// ---------------- common PTX helpers ----------------
__device__ __forceinline__ unsigned f2tf(float x) {
    unsigned r; asm("cvt.rna.tf32.f32 %0, %1;" : "=r"(r) : "f"(x)); return r;
}
__device__ __forceinline__ void mma8(float c[4], const unsigned a[4], const unsigned b[2]) {
    asm volatile(
        "mma.sync.aligned.m16n8k8.row.col.f32.tf32.tf32.f32 "
        "{%0,%1,%2,%3}, {%4,%5,%6,%7}, {%8,%9}, {%0,%1,%2,%3};\n"
        : "+f"(c[0]), "+f"(c[1]), "+f"(c[2]), "+f"(c[3])
        : "r"(a[0]), "r"(a[1]), "r"(a[2]), "r"(a[3]), "r"(b[0]), "r"(b[1]));
}
// fp16-accumulator HMMA: D,C are 2 b32 regs (4 halves)
__device__ __forceinline__ void mma16hh(unsigned c[2], const unsigned a[4], const unsigned b[2]) {
    asm volatile(
        "mma.sync.aligned.m16n8k16.row.col.f16.f16.f16.f16 "
        "{%0,%1}, {%2,%3,%4,%5}, {%6,%7}, {%0,%1};\n"
        : "+r"(c[0]), "+r"(c[1])
        : "r"(a[0]), "r"(a[1]), "r"(a[2]), "r"(a[3]), "r"(b[0]), "r"(b[1]));
}
__device__ __forceinline__ void cpa16(const void* s, const void* g) {
    unsigned sa = (unsigned)__cvta_generic_to_shared(s);
    asm volatile("cp.async.cg.shared.global [%0], [%1], 16;" :: "r"(sa), "l"(g));
}
__device__ __forceinline__ uint32_t smem_u32(const void* p) {
    return (uint32_t)__cvta_generic_to_shared(p);
}
__device__ __forceinline__ void ldm_x4(unsigned& r0, unsigned& r1, unsigned& r2, unsigned& r3,
                                       uint32_t addr) {
    asm volatile("ldmatrix.sync.aligned.m8n8.x4.shared.b16 {%0,%1,%2,%3}, [%4];"
                 : "=r"(r0), "=r"(r1), "=r"(r2), "=r"(r3) : "r"(addr));
}

// ---------------- TN tf32 GEMM (single tf32): C[m][n] = sum_k A[k][m]*B[k][n] ----------------
#define BM  64
#define BN  128
#define BKK 16
#define STG 3
#define APAD 72
#define BPAD 136

__global__ void __launch_bounds__(256) gemm_tn(
    const float* __restrict__ A, long long Abs, int lda,
    const float* __restrict__ B, long long Bbs, int ldb,
    float* __restrict__ C, long long Cbs, int ldc,
    int K)
{
    __shared__ float As[STG][BKK][APAD];
    __shared__ float Bs[STG][BKK][BPAD];

    int n = blockIdx.z;
    A += (size_t)n * Abs; B += (size_t)n * Bbs; C += (size_t)n * Cbs;

    int m_blk = blockIdx.x * BM, n_blk = blockIdx.y * BN;
    int tid = threadIdx.x, warp = tid >> 5, lane = tid & 31;
    int wm = (warp >> 2) * 32, wn = (warp & 3) * 32;
    int lr = lane >> 2, lc = lane & 3;

    float c[2][4][4];
#pragma unroll
    for (int i = 0; i < 2; ++i)
#pragma unroll
        for (int j = 0; j < 4; ++j)
#pragma unroll
            for (int q = 0; q < 4; ++q) c[i][j][q] = 0.f;

    int ar = tid >> 4, ac = (tid & 15) << 2;
    int KT = K / BKK;

    auto issue = [&](int kt, int buf) {
        cpa16(&As[buf][ar][ac], A + (size_t)(kt * BKK + ar) * lda + m_blk + ac);
#pragma unroll
        for (int i = 0; i < 2; ++i) {
            int idx = tid + (i << 8);
            int br = idx >> 5, bc = (idx & 31) << 2;
            cpa16(&Bs[buf][br][bc], B + (size_t)(kt * BKK + br) * ldb + n_blk + bc);
        }
    };

    for (int s = 0; s < STG - 1; ++s) {
        if (s < KT) issue(s, s);
        asm volatile("cp.async.commit_group;");
    }

    for (int kt = 0; kt < KT; ++kt) {
        asm volatile("cp.async.wait_group %0;" :: "n"(STG - 2));
        __syncthreads();
        int buf = kt % STG;

#pragma unroll
        for (int kk = 0; kk < BKK; kk += 8) {
            unsigned ah[2][4], bh[4][2];
#pragma unroll
            for (int mt = 0; mt < 2; ++mt) {
                int mb = wm + mt * 16;
                ah[mt][0] = f2tf(As[buf][kk + lc][mb + lr]);
                ah[mt][1] = f2tf(As[buf][kk + lc][mb + lr + 8]);
                ah[mt][2] = f2tf(As[buf][kk + lc + 4][mb + lr]);
                ah[mt][3] = f2tf(As[buf][kk + lc + 4][mb + lr + 8]);
            }
#pragma unroll
            for (int nt = 0; nt < 4; ++nt) {
                int nb = wn + nt * 8;
                bh[nt][0] = f2tf(Bs[buf][kk + lc][nb + lr]);
                bh[nt][1] = f2tf(Bs[buf][kk + lc + 4][nb + lr]);
            }
#pragma unroll
            for (int mt = 0; mt < 2; ++mt)
#pragma unroll
                for (int nt = 0; nt < 4; ++nt)
                    mma8(c[mt][nt], ah[mt], bh[nt]);
        }
        __syncthreads();
        int nx = kt + STG - 1;
        if (nx < KT) issue(nx, nx % STG);
        asm volatile("cp.async.commit_group;");
    }

#pragma unroll
    for (int mt = 0; mt < 2; ++mt)
#pragma unroll
        for (int nt = 0; nt < 4; ++nt) {
            int r0 = m_blk + wm + mt * 16 + lr;
            int c0 = n_blk + wn + nt * 8 + lc * 2;
            *(float2*)(C + (size_t)r0 * ldc + c0)       = make_float2(c[mt][nt][0], c[mt][nt][1]);
            *(float2*)(C + (size_t)(r0 + 8) * ldc + c0) = make_float2(c[mt][nt][2], c[mt][nt][3]);
        }
}

// ---------------- E': P^T[j][i] = exp(sum_c K[c][j] Q[c][i]); z_i += column sums ----------------
// single tf32 pass (fp16-P quantization dominates the error budget)
__global__ void __launch_bounds__(256) gemm_e(
    const float* __restrict__ A, long long Abs, int lda,
    const float* __restrict__ B, long long Bbs, int ldb,
    __half* __restrict__ C, long long Cbs, int ldc,
    float* __restrict__ gz)
{
    __shared__ float As[STG][BKK][APAD];
    __shared__ float Bs[STG][BKK][BPAD];
    __shared__ float zpart[BN];

    int n = blockIdx.z;
    A += (size_t)n * Abs; B += (size_t)n * Bbs; C += (size_t)n * Cbs;

    int m_blk = blockIdx.y * BM, n_blk = blockIdx.x * BN;
    int tid = threadIdx.x, warp = tid >> 5, lane = tid & 31;
    int wm = (warp >> 2) * 32, wn = (warp & 3) * 32;
    int lr = lane >> 2, lc = lane & 3;

    float c[2][4][4];
#pragma unroll
    for (int i = 0; i < 2; ++i)
#pragma unroll
        for (int j = 0; j < 4; ++j)
#pragma unroll
            for (int q = 0; q < 4; ++q) c[i][j][q] = 0.f;

    if (tid < BN) zpart[tid] = 0.f;

    int ar = tid >> 4, ac = (tid & 15) << 2;
    const int KT = 32 / BKK;  // 2

    auto issue = [&](int kt, int buf) {
        cpa16(&As[buf][ar][ac], A + (size_t)(kt * BKK + ar) * lda + m_blk + ac);
#pragma unroll
        for (int i = 0; i < 2; ++i) {
            int idx = tid + (i << 8);
            int br = idx >> 5, bc = (idx & 31) << 2;
            cpa16(&Bs[buf][br][bc], B + (size_t)(kt * BKK + br) * ldb + n_blk + bc);
        }
    };

    for (int s = 0; s < STG - 1; ++s) {
        if (s < KT) issue(s, s);
        asm volatile("cp.async.commit_group;");
    }

    for (int kt = 0; kt < KT; ++kt) {
        asm volatile("cp.async.wait_group %0;" :: "n"(STG - 2));
        __syncthreads();
        int buf = kt % STG;
#pragma unroll
        for (int kk = 0; kk < BKK; kk += 8) {
            unsigned ah[2][4], bh[4][2];
#pragma unroll
            for (int mt = 0; mt < 2; ++mt) {
                int mb = wm + mt * 16;
                ah[mt][0] = f2tf(As[buf][kk + lc][mb + lr]);
                ah[mt][1] = f2tf(As[buf][kk + lc][mb + lr + 8]);
                ah[mt][2] = f2tf(As[buf][kk + lc + 4][mb + lr]);
                ah[mt][3] = f2tf(As[buf][kk + lc + 4][mb + lr + 8]);
            }
#pragma unroll
            for (int nt = 0; nt < 4; ++nt) {
                int nb = wn + nt * 8;
                bh[nt][0] = f2tf(Bs[buf][kk + lc][nb + lr]);
                bh[nt][1] = f2tf(Bs[buf][kk + lc + 4][nb + lr]);
            }
#pragma unroll
            for (int mt = 0; mt < 2; ++mt)
#pragma unroll
                for (int nt = 0; nt < 4; ++nt)
                    mma8(c[mt][nt], ah[mt], bh[nt]);
        }
        __syncthreads();
        int nx = kt + STG - 1;
        if (nx < KT) issue(nx, nx % STG);
        asm volatile("cp.async.commit_group;");
    }

#pragma unroll
    for (int mt = 0; mt < 2; ++mt)
#pragma unroll
        for (int nt = 0; nt < 4; ++nt) {
#pragma unroll
            for (int q = 0; q < 4; ++q) c[mt][nt][q] = __expf(c[mt][nt][q]);
            int r0 = m_blk + wm + mt * 16 + lr;
            int c0 = n_blk + wn + nt * 8 + lc * 2;
            *(__half2*)(C + (size_t)r0 * ldc + c0) =
                __floats2half2_rn(c[mt][nt][0], c[mt][nt][1]);
            *(__half2*)(C + (size_t)(r0 + 8) * ldc + c0) =
                __floats2half2_rn(c[mt][nt][2], c[mt][nt][3]);
        }
#pragma unroll
    for (int nt = 0; nt < 4; ++nt) {
#pragma unroll
        for (int cp = 0; cp < 2; ++cp) {
            float v = c[0][nt][cp] + c[0][nt][cp + 2] + c[1][nt][cp] + c[1][nt][cp + 2];
            atomicAdd(&zpart[wn + nt * 8 + 2 * lc + cp], v);
        }
    }
    __syncthreads();
    if (tid < BN) atomicAdd(&gz[(size_t)n * HW + n_blk + tid], zpart[tid]);
}

// ---------------- zscale: Uh[o][i] = fp16( U[o][i] * 2^12 / z_i ) ----------------
__global__ void zscale() {
    int n = blockIdx.y;
    int idx = blockIdx.x * blockDim.x + threadIdx.x;   // pair index
    int base = idx * 2;
    int o = base >> 12;          // /4096
    int i = base & (HW - 1);
    const float* u = g_QKU + ((size_t)n * MALL + 64 + o) * HW + i;
    const float* z = g_Z + (size_t)n * HW + i;
    float a = u[0] * (USCALE / z[0]);
    float b = u[1] * (USCALE / z[1]);
    *(__half2*)(g_Uh + ((size_t)n * CC + o) * HW + i) = __floats2half2_rn(a, b);
}

// ================= K5 v8: NT fp16 GEMM, 128x64 tiles, fp16 accumulators + f32 spill =================
// out[o][j] = 2^-12 * sum_i Uh[o][i] * Ph[j][i]   (both operands K-major)
// fp16 C-regs probe the HMMA.F16 dual-rate hypothesis; spill to f32 every 8 kt (k=512).
#define K5_BM   128
#define K5_BN   64
#define K5_BK   64
#define K5_STG  3
#define K5_A_BYTES 16384                     // 128 rows x 128 B
#define K5_B_BYTES 8192                      // 64 rows x 128 B
#define K5_STAGE   (K5_A_BYTES + K5_B_BYTES) // 24576
#define K5_SMEM    (K5_STG * K5_STAGE)       // 73728 bytes -> occ 3

#define SWZ(off) ((off) ^ (((off) >> 3) & 0x70))

__global__ void __launch_bounds__(256, 3) gemm_nt_f16_v8(
    const __half* __restrict__ A, const __half* __restrict__ B,
    float* __restrict__ C)
{
    extern __shared__ __align__(1024) char dsm[];
    uint32_t sbase = smem_u32(dsm);

    int n = blockIdx.z;
    const __half* Ab = A + (size_t)n * CC * HW + (size_t)(blockIdx.x * K5_BM) * HW;
    const __half* Bb = B + (size_t)n * HW * HW + (size_t)(blockIdx.y * K5_BN) * HW;
    float* Cb = C + (size_t)n * CC * HW + (size_t)(blockIdx.x * K5_BM) * HW + blockIdx.y * K5_BN;

    int tid = threadIdx.x, warp = tid >> 5, lane = tid & 31;
    int wm = (warp >> 1) * 32, wn = (warp & 1) * 32;   // 4x2 warp grid of 32x32 tiles
    int gr = lane >> 2, q4 = lane & 3;
    int sub = lane >> 3, rs = lane & 7;

    float c[2][4][4];           // f32 master accumulators
    unsigned ch[2][4][2];       // f16 working accumulators (half2 x2)
#pragma unroll
    for (int i = 0; i < 2; ++i)
#pragma unroll
        for (int j = 0; j < 4; ++j) {
#pragma unroll
            for (int p = 0; p < 4; ++p) c[i][j][p] = 0.f;
            ch[i][j][0] = 0u; ch[i][j][1] = 0u;
        }

    const int KT = HW / K5_BK;   // 64

    auto issue = [&](int kt, int s) {
        int k0 = kt * K5_BK;
        char* abase = dsm + (size_t)s * K5_STAGE;
        char* bbase = abase + K5_A_BYTES;
#pragma unroll
        for (int j = 0; j < 4; ++j) {
            int id = tid + (j << 8);
            int row = id >> 3, chk = id & 7;
            uint32_t so = SWZ((uint32_t)(row * 128 + chk * 16));
            cpa16(abase + so, Ab + (size_t)row * HW + k0 + chk * 8);
        }
#pragma unroll
        for (int j = 0; j < 2; ++j) {
            int id = tid + (j << 8);
            int row = id >> 3, chk = id & 7;
            uint32_t so = SWZ((uint32_t)(row * 128 + chk * 16));
            cpa16(bbase + so, Bb + (size_t)row * HW + k0 + chk * 8);
        }
    };

    issue(0, 0);
    asm volatile("cp.async.commit_group;");
    issue(1, 1);
    asm volatile("cp.async.commit_group;");

    int arow0 = wm + (sub & 1) * 8 + rs;
    int au    = sub >> 1;
    int brow0 = wn + (sub >> 1) * 8 + rs;
    int bu    = sub & 1;

    for (int kt = 0; kt < KT; ++kt) {
        asm volatile("cp.async.wait_group 1;");
        __syncthreads();
        int nx = kt + 2;
        if (nx < KT) issue(nx, nx % K5_STG);
        asm volatile("cp.async.commit_group;");

        int buf = kt % K5_STG;
        uint32_t aT = sbase + (uint32_t)buf * K5_STAGE;
        uint32_t bT = aT + K5_A_BYTES;

#pragma unroll
        for (int ks = 0; ks < 4; ++ks) {
            unsigned a[2][4], b[4][2];
#pragma unroll
            for (int mt = 0; mt < 2; ++mt) {
                uint32_t addr = aT + SWZ((uint32_t)((arow0 + mt * 16) * 128 + (ks * 2 + au) * 16));
                ldm_x4(a[mt][0], a[mt][1], a[mt][2], a[mt][3], addr);
            }
#pragma unroll
            for (int p = 0; p < 2; ++p) {
                uint32_t addr = bT + SWZ((uint32_t)((brow0 + p * 16) * 128 + (ks * 2 + bu) * 16));
                ldm_x4(b[2 * p][0], b[2 * p][1], b[2 * p + 1][0], b[2 * p + 1][1], addr);
            }
#pragma unroll
            for (int mt = 0; mt < 2; ++mt)
#pragma unroll
                for (int nt = 0; nt < 4; ++nt)
                    mma16hh(ch[mt][nt], a[mt], b[nt]);
        }

        // spill fp16 accumulators into f32 masters every 8 kt (k-span 512)
        if ((kt & 7) == 7) {
#pragma unroll
            for (int mt = 0; mt < 2; ++mt)
#pragma unroll
                for (int nt = 0; nt < 4; ++nt) {
                    float2 v0 = __half22float2(*(__half2*)&ch[mt][nt][0]);
                    float2 v1 = __half22float2(*(__half2*)&ch[mt][nt][1]);
                    c[mt][nt][0] += v0.x; c[mt][nt][1] += v0.y;
                    c[mt][nt][2] += v1.x; c[mt][nt][3] += v1.y;
                    ch[mt][nt][0] = 0u; ch[mt][nt][1] = 0u;
                }
        }
    }

#pragma unroll
    for (int mt = 0; mt < 2; ++mt) {
        int r0 = wm + mt * 16 + gr;
#pragma unroll
        for (int nt = 0; nt < 4; ++nt) {
            int c0 = wn + nt * 8 + 2 * q4;
            *(float2*)(Cb + (size_t)r0 * HW + c0) =
                make_float2(c[mt][nt][0] * UNSCALE, c[mt][nt][1] * UNSCALE);
            *(float2*)(Cb + (size_t)(r0 + 8) * HW + c0) =
                make_float2(c[mt][nt][2] * UNSCALE, c[mt][nt][3] * UNSCALE);
        }
    }
}

// ---------------- launch ----------------
extern "C" void kernel_launch(void* const* d_in, const int* in_sizes, int n_in,
                              void* d_out, int out_size) {
    const float* x  = (const float*)d_in[0];
    const float* Wq = (const float*)d_in[1];
    const float* Wk = (const float*)d_in[2];
    const float* Wv = (const float*)d_in[3];
    const float* Wo = (const float*)d_in[4];
    const float* gm = (const float*)d_in[5];
    float* out = (float*)d_out;

    float *wall, *qku, *gz;
    __half *uh, *ph;
    cudaGetSymbolAddress((void**)&wall, g_WallT);
    cudaGetSymbolAddress((void**)&qku,  g_QKU);
    cudaGetSymbolAddress((void**)&gz,   g_Z);
    cudaGetSymbolAddress((void**)&uh,   g_Uh);
    cudaGetSymbolAddress((void**)&ph,   g_Ph);

    // K0: combined weights (gamma folded into U-matrix) + zero z accumulators
    build_wall<<<MALL, 256>>>(Wq, Wk, Wv, Wo, gm);

    // K1: QKU[n] = WallT^T * x[n]
    gemm_tn<<<dim3(MALL / BM, HW / BN, NB), 256>>>(
        wall, 0LL, MALL,
        x, (long long)CC * HW, HW,
        qku, (long long)MALL * HW, HW,
        CC);

    // E': P^T = exp(K^T-rows x Q)  (single tf32), fp16 out, z column sums
    gemm_e<<<dim3(HW / BN, HW / BM, NB), 256>>>(
        qku + 32 * HW, (long long)MALL * HW, HW,    // A = K part
        qku,           (long long)MALL * HW, HW,    // B = Q part
        ph, (long long)HW * HW, HW,
        gz);

    // fold 2^12/z into U (column scale), convert to fp16
    zscale<<<dim3(CC * HW / 512, NB), 256>>>();

    // K5 v8: fp16-accumulator probe (128x64 tiles, f32 spill every k=512)
    cudaFuncSetAttribute(gemm_nt_f16_v8, cudaFuncAttributeMaxDynamicSharedMemorySize, K5_SMEM);
    gemm_nt_f16_v8<<<dim3(CC / K5_BM, HW / K5_BN, NB), 256, K5_SMEM>>>(uh, ph, out);
}

// round 13
// speedup vs baseline: 1.1216x; 1.1216x over previous
#include <cuda_runtime.h>
#include <cuda_fp16.h>
#include <cstdint>

#define NB   8
#define CC   256
#define HW   4096
#define MALL 320   // 32 Q rows + 32 K rows + 256 U rows

#define USCALE    4096.0f          // 2^12, lifts U''/z out of fp16 subnormal range
#define UNSCALE   (1.0f / 4096.0f)

// ---------------- device scratch ----------------
__device__ __align__(128) float g_WallT[CC * MALL];                 // [c][m]
__device__ __align__(128) float g_QKU[(size_t)NB * MALL * HW];      // [n][m][l]
__device__ __align__(128) float g_Z[(size_t)NB * HW];               // row sums z_i
__device__ __align__(128) __half g_Uh[(size_t)NB * CC * HW];        // U''·2^12 [n][o][i]
__device__ __align__(128) __half g_Ph[(size_t)NB * HW * HW];        // P^T [n][j][i] fp16

// ---------------- K0: build combined weight matrix (transposed) + zero g_Z ----------------
__global__ void build_wall(const float* __restrict__ Wq, const float* __restrict__ Wk,
                           const float* __restrict__ Wv, const float* __restrict__ Wo,
                           const float* __restrict__ gammap) {
    int m = blockIdx.x;      // 0..319
    int c = threadIdx.x;     // 0..255
    int idx = m * 256 + c;
    if (idx < NB * HW) g_Z[idx] = 0.f;    // folded memset
    float v;
    if (m < 32) {
        v = Wq[m * CC + c];
    } else if (m < 64) {
        v = Wk[(m - 32) * CC + c];
    } else {
        int o = m - 64;
        float acc = 0.f;
        for (int t = 0; t < CC; ++t)
            acc = fmaf(Wo[o * CC + t], Wv[t * CC + c], acc);
        v = acc * gammap[0];
    }
    g_WallT[c * MALL + m] = v;
}

// ---------------- common PTX helpers ----------------
__device__ __forceinline__ unsigned packh2(float lo, float hi) {
    __half2 h = __floats2half2_rn(lo, hi);
    return *(unsigned*)&h;
}
__device__ __forceinline__ void mma16h(float c[4], const unsigned a[4], const unsigned b[2]) {
    asm volatile(
        "mma.sync.aligned.m16n8k16.row.col.f32.f16.f16.f32 "
        "{%0,%1,%2,%3}, {%4,%5,%6,%7}, {%8,%9}, {%0,%1,%2,%3};\n"
        : "+f"(c[0]), "+f"(c[1]), "+f"(c[2]), "+f"(c[3])
        : "r"(a[0]), "r"(a[1]), "r"(a[2]), "r"(a[3]), "r"(b[0]), "r"(b[1]));
}
__device__ __forceinline__ void cpa16(const void* s, const void* g) {
    unsigned sa = (unsigned)__cvta_generic_to_shared(s);
    asm volatile("cp.async.cg.shared.global [%0], [%1], 16;" :: "r"(sa), "l"(g));
}
__device__ __forceinline__ uint32_t smem_u32(const void* p) {
    return (uint32_t)__cvta_generic_to_shared(p);
}
__device__ __forceinline__ void ldm_x4(unsigned& r0, unsigned& r1, unsigned& r2, unsigned& r3,
                                       uint32_t addr) {
    asm volatile("ldmatrix.sync.aligned.m8n8.x4.shared.b16 {%0,%1,%2,%3}, [%4];"
                 : "=r"(r0), "=r"(r1), "=r"(r2), "=r"(r3) : "r"(addr));
}

// ---------------- TN fp16-MMA GEMM: C[m][n] = sum_k A[k][m]*B[k][n] (fp32 smem, packed frags) ----------------
#define BM  64
#define BN  128
#define BKK 16
#define STG 3
#define APAD 76    // 2lc-row LDS pattern conflict-free (24lc bank blocks), 16B-aligned rows
#define BPAD 140

__global__ void __launch_bounds__(256) gemm_tn(
    const float* __restrict__ A, long long Abs, int lda,
    const float* __restrict__ B, long long Bbs, int ldb,
    float* __restrict__ C, long long Cbs, int ldc,
    int K)
{
    __shared__ float As[STG][BKK][APAD];
    __shared__ float Bs[STG][BKK][BPAD];

    int n = blockIdx.z;
    A += (size_t)n * Abs; B += (size_t)n * Bbs; C += (size_t)n * Cbs;

    int m_blk = blockIdx.x * BM, n_blk = blockIdx.y * BN;
    int tid = threadIdx.x, warp = tid >> 5, lane = tid & 31;
    int wm = (warp >> 2) * 32, wn = (warp & 3) * 32;
    int lr = lane >> 2, lc = lane & 3;

    float c[2][4][4];
#pragma unroll
    for (int i = 0; i < 2; ++i)
#pragma unroll
        for (int j = 0; j < 4; ++j)
#pragma unroll
            for (int q = 0; q < 4; ++q) c[i][j][q] = 0.f;

    int ar = tid >> 4, ac = (tid & 15) << 2;
    int KT = K / BKK;

    auto issue = [&](int kt, int buf) {
        cpa16(&As[buf][ar][ac], A + (size_t)(kt * BKK + ar) * lda + m_blk + ac);
#pragma unroll
        for (int i = 0; i < 2; ++i) {
            int idx = tid + (i << 8);
            int br = idx >> 5, bc = (idx & 31) << 2;
            cpa16(&Bs[buf][br][bc], B + (size_t)(kt * BKK + br) * ldb + n_blk + bc);
        }
    };

    for (int s = 0; s < STG - 1; ++s) {
        if (s < KT) issue(s, s);
        asm volatile("cp.async.commit_group;");
    }

    for (int kt = 0; kt < KT; ++kt) {
        asm volatile("cp.async.wait_group %0;" :: "n"(STG - 2));
        __syncthreads();
        int buf = kt % STG;

        // one k16 fp16 mma round per stage
        unsigned a[2][4], b[4][2];
#pragma unroll
        for (int mt = 0; mt < 2; ++mt) {
            int mb = wm + mt * 16;
            a[mt][0] = packh2(As[buf][2*lc][mb+lr],     As[buf][2*lc+1][mb+lr]);
            a[mt][1] = packh2(As[buf][2*lc][mb+lr+8],   As[buf][2*lc+1][mb+lr+8]);
            a[mt][2] = packh2(As[buf][2*lc+8][mb+lr],   As[buf][2*lc+9][mb+lr]);
            a[mt][3] = packh2(As[buf][2*lc+8][mb+lr+8], As[buf][2*lc+9][mb+lr+8]);
        }
#pragma unroll
        for (int nt = 0; nt < 4; ++nt) {
            int nb = wn + nt * 8;
            b[nt][0] = packh2(Bs[buf][2*lc][nb+lr],   Bs[buf][2*lc+1][nb+lr]);
            b[nt][1] = packh2(Bs[buf][2*lc+8][nb+lr], Bs[buf][2*lc+9][nb+lr]);
        }
#pragma unroll
        for (int mt = 0; mt < 2; ++mt)
#pragma unroll
            for (int nt = 0; nt < 4; ++nt)
                mma16h(c[mt][nt], a[mt], b[nt]);

        __syncthreads();
        int nx = kt + STG - 1;
        if (nx < KT) issue(nx, nx % STG);
        asm volatile("cp.async.commit_group;");
    }

#pragma unroll
    for (int mt = 0; mt < 2; ++mt)
#pragma unroll
        for (int nt = 0; nt < 4; ++nt) {
            int r0 = m_blk + wm + mt * 16 + lr;
            int c0 = n_blk + wn + nt * 8 + lc * 2;
            *(float2*)(C + (size_t)r0 * ldc + c0)       = make_float2(c[mt][nt][0], c[mt][nt][1]);
            *(float2*)(C + (size_t)(r0 + 8) * ldc + c0) = make_float2(c[mt][nt][2], c[mt][nt][3]);
        }
}

// ---------------- E': P^T[j][i] = exp(sum_c K[c][j] Q[c][i]); z_i += column sums ----------------
// fp16 mma16 (packed fragments from fp32 smem)
__global__ void __launch_bounds__(256) gemm_e(
    const float* __restrict__ A, long long Abs, int lda,
    const float* __restrict__ B, long long Bbs, int ldb,
    __half* __restrict__ C, long long Cbs, int ldc,
    float* __restrict__ gz)
{
    __shared__ float As[STG][BKK][APAD];
    __shared__ float Bs[STG][BKK][BPAD];
    __shared__ float zpart[BN];

    int n = blockIdx.z;
    A += (size_t)n * Abs; B += (size_t)n * Bbs; C += (size_t)n * Cbs;

    int m_blk = blockIdx.y * BM, n_blk = blockIdx.x * BN;
    int tid = threadIdx.x, warp = tid >> 5, lane = tid & 31;
    int wm = (warp >> 2) * 32, wn = (warp & 3) * 32;
    int lr = lane >> 2, lc = lane & 3;

    float c[2][4][4];
#pragma unroll
    for (int i = 0; i < 2; ++i)
#pragma unroll
        for (int j = 0; j < 4; ++j)
#pragma unroll
            for (int q = 0; q < 4; ++q) c[i][j][q] = 0.f;

    if (tid < BN) zpart[tid] = 0.f;

    int ar = tid >> 4, ac = (tid & 15) << 2;
    const int KT = 32 / BKK;  // 2

    auto issue = [&](int kt, int buf) {
        cpa16(&As[buf][ar][ac], A + (size_t)(kt * BKK + ar) * lda + m_blk + ac);
#pragma unroll
        for (int i = 0; i < 2; ++i) {
            int idx = tid + (i << 8);
            int br = idx >> 5, bc = (idx & 31) << 2;
            cpa16(&Bs[buf][br][bc], B + (size_t)(kt * BKK + br) * ldb + n_blk + bc);
        }
    };

    for (int s = 0; s < STG - 1; ++s) {
        if (s < KT) issue(s, s);
        asm volatile("cp.async.commit_group;");
    }

    for (int kt = 0; kt < KT; ++kt) {
        asm volatile("cp.async.wait_group %0;" :: "n"(STG - 2));
        __syncthreads();
        int buf = kt % STG;

        unsigned a[2][4], b[4][2];
#pragma unroll
        for (int mt = 0; mt < 2; ++mt) {
            int mb = wm + mt * 16;
            a[mt][0] = packh2(As[buf][2*lc][mb+lr],     As[buf][2*lc+1][mb+lr]);
            a[mt][1] = packh2(As[buf][2*lc][mb+lr+8],   As[buf][2*lc+1][mb+lr+8]);
            a[mt][2] = packh2(As[buf][2*lc+8][mb+lr],   As[buf][2*lc+9][mb+lr]);
            a[mt][3] = packh2(As[buf][2*lc+8][mb+lr+8], As[buf][2*lc+9][mb+lr+8]);
        }
#pragma unroll
        for (int nt = 0; nt < 4; ++nt) {
            int nb = wn + nt * 8;
            b[nt][0] = packh2(Bs[buf][2*lc][nb+lr],   Bs[buf][2*lc+1][nb+lr]);
            b[nt][1] = packh2(Bs[buf][2*lc+8][nb+lr], Bs[buf][2*lc+9][nb+lr]);
        }
#pragma unroll
        for (int mt = 0; mt < 2; ++mt)
#pragma unroll
            for (int nt = 0; nt < 4; ++nt)
                mma16h(c[mt][nt], a[mt], b[nt]);

        __syncthreads();
        int nx = kt + STG - 1;
        if (nx < KT) issue(nx, nx % STG);
        asm volatile("cp.async.commit_group;");
    }

#pragma unroll
    for (int mt = 0; mt < 2; ++mt)
#pragma unroll
        for (int nt = 0; nt < 4; ++nt) {
#pragma unroll
            for (int q = 0; q < 4; ++q) c[mt][nt][q] = __expf(c[mt][nt][q]);
            int r0 = m_blk + wm + mt * 16 + lr;
            int c0 = n_blk + wn + nt * 8 + lc * 2;
            *(__half2*)(C + (size_t)r0 * ldc + c0) =
                __floats2half2_rn(c[mt][nt][0], c[mt][nt][1]);
            *(__half2*)(C + (size_t)(r0 + 8) * ldc + c0) =
                __floats2half2_rn(c[mt][nt][2], c[mt][nt][3]);
        }
#pragma unroll
    for (int nt = 0; nt < 4; ++nt) {
#pragma unroll
        for (int cp = 0; cp < 2; ++cp) {
            float v = c[0][nt][cp] + c[0][nt][cp + 2] + c[1][nt][cp] + c[1][nt][cp + 2];
            atomicAdd(&zpart[wn + nt * 8 + 2 * lc + cp], v);
        }
    }
    __syncthreads();
    if (tid < BN) atomicAdd(&gz[(size_t)n * HW + n_blk + tid], zpart[tid]);
}

// ---------------- zscale: Uh[o][i] = fp16( U[o][i] * 2^12 / z_i ) ----------------
__global__ void zscale() {
    int n = blockIdx.y;
    int idx = blockIdx.x * blockDim.x + threadIdx.x;   // pair index
    int base = idx * 2;
    int o = base >> 12;          // /4096
    int i = base & (HW - 1);
    const float* u = g_QKU + ((size_t)n * MALL + 64 + o) * HW + i;
    const float* z = g_Z + (size_t)n * HW + i;
    float a = u[0] * (USCALE / z[0]);
    float b = u[1] * (USCALE / z[1]);
    *(__half2*)(g_Uh + ((size_t)n * CC + o) * HW + i) = __floats2half2_rn(a, b);
}

// ================= K5 v7 (best known): NT fp16 GEMM, 128x64 tiles, f32 accum =================
#define K5_BM   128
#define K5_BN   64
#define K5_BK   64
#define K5_STG  3
#define K5_A_BYTES 16384                     // 128 rows x 128 B
#define K5_B_BYTES 8192                      // 64 rows x 128 B
#define K5_STAGE   (K5_A_BYTES + K5_B_BYTES) // 24576
#define K5_SMEM    (K5_STG * K5_STAGE)       // 73728 bytes -> occ 3

#define SWZ(off) ((off) ^ (((off) >> 3) & 0x70))

__global__ void __launch_bounds__(256, 3) gemm_nt_f16_v7(
    const __half* __restrict__ A, const __half* __restrict__ B,
    float* __restrict__ C)
{
    extern __shared__ __align__(1024) char dsm[];
    uint32_t sbase = smem_u32(dsm);

    int n = blockIdx.z;
    const __half* Ab = A + (size_t)n * CC * HW + (size_t)(blockIdx.x * K5_BM) * HW;
    const __half* Bb = B + (size_t)n * HW * HW + (size_t)(blockIdx.y * K5_BN) * HW;
    float* Cb = C + (size_t)n * CC * HW + (size_t)(blockIdx.x * K5_BM) * HW + blockIdx.y * K5_BN;

    int tid = threadIdx.x, warp = tid >> 5, lane = tid & 31;
    int wm = (warp >> 1) * 32, wn = (warp & 1) * 32;   // 4x2 warp grid of 32x32 tiles
    int gr = lane >> 2, q4 = lane & 3;
    int sub = lane >> 3, rs = lane & 7;

    float c[2][4][4];
#pragma unroll
    for (int i = 0; i < 2; ++i)
#pragma unroll
        for (int j = 0; j < 4; ++j)
#pragma unroll
            for (int p = 0; p < 4; ++p) c[i][j][p] = 0.f;

    const int KT = HW / K5_BK;   // 64

    auto issue = [&](int kt, int s) {
        int k0 = kt * K5_BK;
        char* abase = dsm + (size_t)s * K5_STAGE;
        char* bbase = abase + K5_A_BYTES;
#pragma unroll
        for (int j = 0; j < 4; ++j) {
            int id = tid + (j << 8);
            int row = id >> 3, ch = id & 7;
            uint32_t so = SWZ((uint32_t)(row * 128 + ch * 16));
            cpa16(abase + so, Ab + (size_t)row * HW + k0 + ch * 8);
        }
#pragma unroll
        for (int j = 0; j < 2; ++j) {
            int id = tid + (j << 8);
            int row = id >> 3, ch = id & 7;
            uint32_t so = SWZ((uint32_t)(row * 128 + ch * 16));
            cpa16(bbase + so, Bb + (size_t)row * HW + k0 + ch * 8);
        }
    };

    issue(0, 0);
    asm volatile("cp.async.commit_group;");
    issue(1, 1);
    asm volatile("cp.async.commit_group;");

    int arow0 = wm + (sub & 1) * 8 + rs;
    int au    = sub >> 1;
    int brow0 = wn + (sub >> 1) * 8 + rs;
    int bu    = sub & 1;

    for (int kt = 0; kt < KT; ++kt) {
        asm volatile("cp.async.wait_group 1;");
        __syncthreads();
        int nx = kt + 2;
        if (nx < KT) issue(nx, nx % K5_STG);
        asm volatile("cp.async.commit_group;");

        int buf = kt % K5_STG;
        uint32_t aT = sbase + (uint32_t)buf * K5_STAGE;
        uint32_t bT = aT + K5_A_BYTES;

#pragma unroll
        for (int ks = 0; ks < 4; ++ks) {
            unsigned a[2][4], b[4][2];
#pragma unroll
            for (int mt = 0; mt < 2; ++mt) {
                uint32_t addr = aT + SWZ((uint32_t)((arow0 + mt * 16) * 128 + (ks * 2 + au) * 16));
                ldm_x4(a[mt][0], a[mt][1], a[mt][2], a[mt][3], addr);
            }
#pragma unroll
            for (int p = 0; p < 2; ++p) {
                uint32_t addr = bT + SWZ((uint32_t)((brow0 + p * 16) * 128 + (ks * 2 + bu) * 16));
                ldm_x4(b[2 * p][0], b[2 * p][1], b[2 * p + 1][0], b[2 * p + 1][1], addr);
            }
#pragma unroll
            for (int mt = 0; mt < 2; ++mt)
#pragma unroll
                for (int nt = 0; nt < 4; ++nt)
                    mma16h(c[mt][nt], a[mt], b[nt]);
        }
    }

#pragma unroll
    for (int mt = 0; mt < 2; ++mt) {
        int r0 = wm + mt * 16 + gr;
#pragma unroll
        for (int nt = 0; nt < 4; ++nt) {
            int c0 = wn + nt * 8 + 2 * q4;
            *(float2*)(Cb + (size_t)r0 * HW + c0) =
                make_float2(c[mt][nt][0] * UNSCALE, c[mt][nt][1] * UNSCALE);
            *(float2*)(Cb + (size_t)(r0 + 8) * HW + c0) =
                make_float2(c[mt][nt][2] * UNSCALE, c[mt][nt][3] * UNSCALE);
        }
    }
}

// ---------------- launch ----------------
extern "C" void kernel_launch(void* const* d_in, const int* in_sizes, int n_in,
                              void* d_out, int out_size) {
    const float* x  = (const float*)d_in[0];
    const float* Wq = (const float*)d_in[1];
    const float* Wk = (const float*)d_in[2];
    const float* Wv = (const float*)d_in[3];
    const float* Wo = (const float*)d_in[4];
    const float* gm = (const float*)d_in[5];
    float* out = (float*)d_out;

    float *wall, *qku, *gz;
    __half *uh, *ph;
    cudaGetSymbolAddress((void**)&wall, g_WallT);
    cudaGetSymbolAddress((void**)&qku,  g_QKU);
    cudaGetSymbolAddress((void**)&gz,   g_Z);
    cudaGetSymbolAddress((void**)&uh,   g_Uh);
    cudaGetSymbolAddress((void**)&ph,   g_Ph);

    // K0: combined weights (gamma folded into U-matrix) + zero z accumulators
    build_wall<<<MALL, 256>>>(Wq, Wk, Wv, Wo, gm);

    // K1: QKU[n] = WallT^T * x[n]  (fp16 mma, fp32 I/O)
    gemm_tn<<<dim3(MALL / BM, HW / BN, NB), 256>>>(
        wall, 0LL, MALL,
        x, (long long)CC * HW, HW,
        qku, (long long)MALL * HW, HW,
        CC);

    // E': P^T = exp(K^T-rows x Q)  (fp16 mma), fp16 out, z column sums
    gemm_e<<<dim3(HW / BN, HW / BM, NB), 256>>>(
        qku + 32 * HW, (long long)MALL * HW, HW,    // A = K part
        qku,           (long long)MALL * HW, HW,    // B = Q part
        ph, (long long)HW * HW, HW,
        gz);

    // fold 2^12/z into U (column scale), convert to fp16
    zscale<<<dim3(CC * HW / 512, NB), 256>>>();

    // K5 v7: fine-grained fp16 NT GEMM (128x64 tiles, f32 accum)
    cudaFuncSetAttribute(gemm_nt_f16_v7, cudaFuncAttributeMaxDynamicSharedMemorySize, K5_SMEM);
    gemm_nt_f16_v7<<<dim3(CC / K5_BM, HW / K5_BN, NB), 256, K5_SMEM>>>(uh, ph, out);
}

// round 14
// speedup vs baseline: 1.1246x; 1.0026x over previous
#include <cuda_runtime.h>
#include <cuda_fp16.h>
#include <cstdint>

#define NB   8
#define CC   256
#define HW   4096
#define MALL 320   // 32 Q rows + 32 K rows + 256 U rows

#define USCALE    4096.0f          // 2^12, lifts U''/z out of fp16 subnormal range
#define UNSCALE   (1.0f / 4096.0f)

// ---------------- device scratch ----------------
__device__ __align__(128) float g_WallT[CC * MALL];                 // [c][m]
__device__ __align__(128) float g_QKU[(size_t)NB * MALL * HW];      // [n][m][l] (only m<64 used now)
__device__ __align__(128) float g_Z[(size_t)NB * HW];               // row sums z_i
__device__ __align__(128) __half g_Uh[(size_t)NB * CC * HW];        // U·2^12 (pre-z, then scaled in place)
__device__ __align__(128) __half g_Ph[(size_t)NB * HW * HW];        // P^T [n][j][i] fp16

// ---------------- K0: build combined weight matrix (transposed) + zero g_Z ----------------
__global__ void build_wall(const float* __restrict__ Wq, const float* __restrict__ Wk,
                           const float* __restrict__ Wv, const float* __restrict__ Wo,
                           const float* __restrict__ gammap) {
    int m = blockIdx.x;      // 0..319
    int c = threadIdx.x;     // 0..255
    int idx = m * 256 + c;
    if (idx < NB * HW) g_Z[idx] = 0.f;    // folded memset
    float v;
    if (m < 32) {
        v = Wq[m * CC + c];
    } else if (m < 64) {
        v = Wk[(m - 32) * CC + c];
    } else {
        int o = m - 64;
        float acc = 0.f;
        for (int t = 0; t < CC; ++t)
            acc = fmaf(Wo[o * CC + t], Wv[t * CC + c], acc);
        v = acc * gammap[0];
    }
    g_WallT[c * MALL + m] = v;
}

// ---------------- common PTX helpers ----------------
__device__ __forceinline__ unsigned packh2(float lo, float hi) {
    __half2 h = __floats2half2_rn(lo, hi);
    return *(unsigned*)&h;
}
__device__ __forceinline__ void mma16h(float c[4], const unsigned a[4], const unsigned b[2]) {
    asm volatile(
        "mma.sync.aligned.m16n8k16.row.col.f32.f16.f16.f32 "
        "{%0,%1,%2,%3}, {%4,%5,%6,%7}, {%8,%9}, {%0,%1,%2,%3};\n"
        : "+f"(c[0]), "+f"(c[1]), "+f"(c[2]), "+f"(c[3])
        : "r"(a[0]), "r"(a[1]), "r"(a[2]), "r"(a[3]), "r"(b[0]), "r"(b[1]));
}
__device__ __forceinline__ void cpa16(const void* s, const void* g) {
    unsigned sa = (unsigned)__cvta_generic_to_shared(s);
    asm volatile("cp.async.cg.shared.global [%0], [%1], 16;" :: "r"(sa), "l"(g));
}
__device__ __forceinline__ uint32_t smem_u32(const void* p) {
    return (uint32_t)__cvta_generic_to_shared(p);
}
__device__ __forceinline__ void ldm_x4(unsigned& r0, unsigned& r1, unsigned& r2, unsigned& r3,
                                       uint32_t addr) {
    asm volatile("ldmatrix.sync.aligned.m8n8.x4.shared.b16 {%0,%1,%2,%3}, [%4];"
                 : "=r"(r0), "=r"(r1), "=r"(r2), "=r"(r3) : "r"(addr));
}

// ---------------- K1: TN fp16-MMA GEMM. Block x=0 -> fp32 Q/K rows; x>0 -> fp16 U·2^12 ----------------
#define BM  64
#define BN  128
#define BKK 16
#define STG 3
#define APAD 76
#define BPAD 140

__global__ void __launch_bounds__(256) gemm_tn(
    const float* __restrict__ A, int lda,
    const float* __restrict__ B, long long Bbs, int ldb,
    float* __restrict__ Cqk, long long Cbs, int ldc,
    __half* __restrict__ Cu, long long Ubs,
    int K)
{
    __shared__ float As[STG][BKK][APAD];
    __shared__ float Bs[STG][BKK][BPAD];

    int n = blockIdx.z;
    B += (size_t)n * Bbs;

    int m_blk = blockIdx.x * BM, n_blk = blockIdx.y * BN;
    int tid = threadIdx.x, warp = tid >> 5, lane = tid & 31;
    int wm = (warp >> 2) * 32, wn = (warp & 3) * 32;
    int lr = lane >> 2, lc = lane & 3;

    float c[2][4][4];
#pragma unroll
    for (int i = 0; i < 2; ++i)
#pragma unroll
        for (int j = 0; j < 4; ++j)
#pragma unroll
            for (int q = 0; q < 4; ++q) c[i][j][q] = 0.f;

    int ar = tid >> 4, ac = (tid & 15) << 2;
    int KT = K / BKK;

    auto issue = [&](int kt, int buf) {
        cpa16(&As[buf][ar][ac], A + (size_t)(kt * BKK + ar) * lda + m_blk + ac);
#pragma unroll
        for (int i = 0; i < 2; ++i) {
            int idx = tid + (i << 8);
            int br = idx >> 5, bc = (idx & 31) << 2;
            cpa16(&Bs[buf][br][bc], B + (size_t)(kt * BKK + br) * ldb + n_blk + bc);
        }
    };

    for (int s = 0; s < STG - 1; ++s) {
        if (s < KT) issue(s, s);
        asm volatile("cp.async.commit_group;");
    }

    for (int kt = 0; kt < KT; ++kt) {
        asm volatile("cp.async.wait_group %0;" :: "n"(STG - 2));
        __syncthreads();
        int buf = kt % STG;

        unsigned a[2][4], b[4][2];
#pragma unroll
        for (int mt = 0; mt < 2; ++mt) {
            int mb = wm + mt * 16;
            a[mt][0] = packh2(As[buf][2*lc][mb+lr],     As[buf][2*lc+1][mb+lr]);
            a[mt][1] = packh2(As[buf][2*lc][mb+lr+8],   As[buf][2*lc+1][mb+lr+8]);
            a[mt][2] = packh2(As[buf][2*lc+8][mb+lr],   As[buf][2*lc+9][mb+lr]);
            a[mt][3] = packh2(As[buf][2*lc+8][mb+lr+8], As[buf][2*lc+9][mb+lr+8]);
        }
#pragma unroll
        for (int nt = 0; nt < 4; ++nt) {
            int nb = wn + nt * 8;
            b[nt][0] = packh2(Bs[buf][2*lc][nb+lr],   Bs[buf][2*lc+1][nb+lr]);
            b[nt][1] = packh2(Bs[buf][2*lc+8][nb+lr], Bs[buf][2*lc+9][nb+lr]);
        }
#pragma unroll
        for (int mt = 0; mt < 2; ++mt)
#pragma unroll
            for (int nt = 0; nt < 4; ++nt)
                mma16h(c[mt][nt], a[mt], b[nt]);

        __syncthreads();
        int nx = kt + STG - 1;
        if (nx < KT) issue(nx, nx % STG);
        asm volatile("cp.async.commit_group;");
    }

    if (blockIdx.x == 0) {
        // Q/K rows: fp32 to g_QKU
        float* C = Cqk + (size_t)n * Cbs;
#pragma unroll
        for (int mt = 0; mt < 2; ++mt)
#pragma unroll
            for (int nt = 0; nt < 4; ++nt) {
                int r0 = m_blk + wm + mt * 16 + lr;
                int c0 = n_blk + wn + nt * 8 + lc * 2;
                *(float2*)(C + (size_t)r0 * ldc + c0)       = make_float2(c[mt][nt][0], c[mt][nt][1]);
                *(float2*)(C + (size_t)(r0 + 8) * ldc + c0) = make_float2(c[mt][nt][2], c[mt][nt][3]);
            }
    } else {
        // U rows: fp16 * 2^12 (pre-z) to g_Uh
        __half* U = Cu + (size_t)n * Ubs;
#pragma unroll
        for (int mt = 0; mt < 2; ++mt)
#pragma unroll
            for (int nt = 0; nt < 4; ++nt) {
                int r0 = m_blk - 64 + wm + mt * 16 + lr;
                int c0 = n_blk + wn + nt * 8 + lc * 2;
                *(__half2*)(U + (size_t)r0 * HW + c0) =
                    __floats2half2_rn(c[mt][nt][0] * USCALE, c[mt][nt][1] * USCALE);
                *(__half2*)(U + (size_t)(r0 + 8) * HW + c0) =
                    __floats2half2_rn(c[mt][nt][2] * USCALE, c[mt][nt][3] * USCALE);
            }
    }
}

// ---------------- E': P^T[j][i] = exp(sum_c K[c][j] Q[c][i]); z_i += column sums ----------------
__global__ void __launch_bounds__(256) gemm_e(
    const float* __restrict__ A, long long Abs, int lda,
    const float* __restrict__ B, long long Bbs, int ldb,
    __half* __restrict__ C, long long Cbs, int ldc,
    float* __restrict__ gz)
{
    __shared__ float As[STG][BKK][APAD];
    __shared__ float Bs[STG][BKK][BPAD];
    __shared__ float zpart[BN];

    int n = blockIdx.z;
    A += (size_t)n * Abs; B += (size_t)n * Bbs; C += (size_t)n * Cbs;

    int m_blk = blockIdx.y * BM, n_blk = blockIdx.x * BN;
    int tid = threadIdx.x, warp = tid >> 5, lane = tid & 31;
    int wm = (warp >> 2) * 32, wn = (warp & 3) * 32;
    int lr = lane >> 2, lc = lane & 3;

    float c[2][4][4];
#pragma unroll
    for (int i = 0; i < 2; ++i)
#pragma unroll
        for (int j = 0; j < 4; ++j)
#pragma unroll
            for (int q = 0; q < 4; ++q) c[i][j][q] = 0.f;

    if (tid < BN) zpart[tid] = 0.f;

    int ar = tid >> 4, ac = (tid & 15) << 2;
    const int KT = 32 / BKK;  // 2

    auto issue = [&](int kt, int buf) {
        cpa16(&As[buf][ar][ac], A + (size_t)(kt * BKK + ar) * lda + m_blk + ac);
#pragma unroll
        for (int i = 0; i < 2; ++i) {
            int idx = tid + (i << 8);
            int br = idx >> 5, bc = (idx & 31) << 2;
            cpa16(&Bs[buf][br][bc], B + (size_t)(kt * BKK + br) * ldb + n_blk + bc);
        }
    };

    for (int s = 0; s < STG - 1; ++s) {
        if (s < KT) issue(s, s);
        asm volatile("cp.async.commit_group;");
    }

    for (int kt = 0; kt < KT; ++kt) {
        asm volatile("cp.async.wait_group %0;" :: "n"(STG - 2));
        __syncthreads();
        int buf = kt % STG;

        unsigned a[2][4], b[4][2];
#pragma unroll
        for (int mt = 0; mt < 2; ++mt) {
            int mb = wm + mt * 16;
            a[mt][0] = packh2(As[buf][2*lc][mb+lr],     As[buf][2*lc+1][mb+lr]);
            a[mt][1] = packh2(As[buf][2*lc][mb+lr+8],   As[buf][2*lc+1][mb+lr+8]);
            a[mt][2] = packh2(As[buf][2*lc+8][mb+lr],   As[buf][2*lc+9][mb+lr]);
            a[mt][3] = packh2(As[buf][2*lc+8][mb+lr+8], As[buf][2*lc+9][mb+lr+8]);
        }
#pragma unroll
        for (int nt = 0; nt < 4; ++nt) {
            int nb = wn + nt * 8;
            b[nt][0] = packh2(Bs[buf][2*lc][nb+lr],   Bs[buf][2*lc+1][nb+lr]);
            b[nt][1] = packh2(Bs[buf][2*lc+8][nb+lr], Bs[buf][2*lc+9][nb+lr]);
        }
#pragma unroll
        for (int mt = 0; mt < 2; ++mt)
#pragma unroll
            for (int nt = 0; nt < 4; ++nt)
                mma16h(c[mt][nt], a[mt], b[nt]);

        __syncthreads();
        int nx = kt + STG - 1;
        if (nx < KT) issue(nx, nx % STG);
        asm volatile("cp.async.commit_group;");
    }

#pragma unroll
    for (int mt = 0; mt < 2; ++mt)
#pragma unroll
        for (int nt = 0; nt < 4; ++nt) {
#pragma unroll
            for (int q = 0; q < 4; ++q) c[mt][nt][q] = __expf(c[mt][nt][q]);
            int r0 = m_blk + wm + mt * 16 + lr;
            int c0 = n_blk + wn + nt * 8 + lc * 2;
            *(__half2*)(C + (size_t)r0 * ldc + c0) =
                __floats2half2_rn(c[mt][nt][0], c[mt][nt][1]);
            *(__half2*)(C + (size_t)(r0 + 8) * ldc + c0) =
                __floats2half2_rn(c[mt][nt][2], c[mt][nt][3]);
        }
#pragma unroll
    for (int nt = 0; nt < 4; ++nt) {
#pragma unroll
        for (int cp = 0; cp < 2; ++cp) {
            float v = c[0][nt][cp] + c[0][nt][cp + 2] + c[1][nt][cp] + c[1][nt][cp + 2];
            atomicAdd(&zpart[wn + nt * 8 + 2 * lc + cp], v);
        }
    }
    __syncthreads();
    if (tid < BN) atomicAdd(&gz[(size_t)n * HW + n_blk + tid], zpart[tid]);
}

// ---------------- zscale v2: Uh[o][i] *= 1/z_i  (fp16 in place) ----------------
__global__ void zscale() {
    int n = blockIdx.y;
    int idx = blockIdx.x * blockDim.x + threadIdx.x;   // half2 index
    int base = idx * 2;
    int o = base >> 12;          // /4096
    int i = base & (HW - 1);
    __half2* u = (__half2*)(g_Uh + ((size_t)n * CC + o) * HW + i);
    const float* z = g_Z + (size_t)n * HW + i;
    float2 v = __half22float2(*u);
    v.x /= z[0];
    v.y /= z[1];
    *u = __floats2half2_rn(v.x, v.y);
}

// ================= K5 v7 (at HMMA issue floor): NT fp16 GEMM, 128x64 tiles, f32 accum =================
#define K5_BM   128
#define K5_BN   64
#define K5_BK   64
#define K5_STG  3
#define K5_A_BYTES 16384                     // 128 rows x 128 B
#define K5_B_BYTES 8192                      // 64 rows x 128 B
#define K5_STAGE   (K5_A_BYTES + K5_B_BYTES) // 24576
#define K5_SMEM    (K5_STG * K5_STAGE)       // 73728 bytes -> occ 3

#define SWZ(off) ((off) ^ (((off) >> 3) & 0x70))

__global__ void __launch_bounds__(256, 3) gemm_nt_f16_v7(
    const __half* __restrict__ A, const __half* __restrict__ B,
    float* __restrict__ C)
{
    extern __shared__ __align__(1024) char dsm[];
    uint32_t sbase = smem_u32(dsm);

    int n = blockIdx.z;
    const __half* Ab = A + (size_t)n * CC * HW + (size_t)(blockIdx.x * K5_BM) * HW;
    const __half* Bb = B + (size_t)n * HW * HW + (size_t)(blockIdx.y * K5_BN) * HW;
    float* Cb = C + (size_t)n * CC * HW + (size_t)(blockIdx.x * K5_BM) * HW + blockIdx.y * K5_BN;

    int tid = threadIdx.x, warp = tid >> 5, lane = tid & 31;
    int wm = (warp >> 1) * 32, wn = (warp & 1) * 32;   // 4x2 warp grid of 32x32 tiles
    int gr = lane >> 2, q4 = lane & 3;
    int sub = lane >> 3, rs = lane & 7;

    float c[2][4][4];
#pragma unroll
    for (int i = 0; i < 2; ++i)
#pragma unroll
        for (int j = 0; j < 4; ++j)
#pragma unroll
            for (int p = 0; p < 4; ++p) c[i][j][p] = 0.f;

    const int KT = HW / K5_BK;   // 64

    auto issue = [&](int kt, int s) {
        int k0 = kt * K5_BK;
        char* abase = dsm + (size_t)s * K5_STAGE;
        char* bbase = abase + K5_A_BYTES;
#pragma unroll
        for (int j = 0; j < 4; ++j) {
            int id = tid + (j << 8);
            int row = id >> 3, ch = id & 7;
            uint32_t so = SWZ((uint32_t)(row * 128 + ch * 16));
            cpa16(abase + so, Ab + (size_t)row * HW + k0 + ch * 8);
        }
#pragma unroll
        for (int j = 0; j < 2; ++j) {
            int id = tid + (j << 8);
            int row = id >> 3, ch = id & 7;
            uint32_t so = SWZ((uint32_t)(row * 128 + ch * 16));
            cpa16(bbase + so, Bb + (size_t)row * HW + k0 + ch * 8);
        }
    };

    issue(0, 0);
    asm volatile("cp.async.commit_group;");
    issue(1, 1);
    asm volatile("cp.async.commit_group;");

    int arow0 = wm + (sub & 1) * 8 + rs;
    int au    = sub >> 1;
    int brow0 = wn + (sub >> 1) * 8 + rs;
    int bu    = sub & 1;

    for (int kt = 0; kt < KT; ++kt) {
        asm volatile("cp.async.wait_group 1;");
        __syncthreads();
        int nx = kt + 2;
        if (nx < KT) issue(nx, nx % K5_STG);
        asm volatile("cp.async.commit_group;");

        int buf = kt % K5_STG;
        uint32_t aT = sbase + (uint32_t)buf * K5_STAGE;
        uint32_t bT = aT + K5_A_BYTES;

#pragma unroll
        for (int ks = 0; ks < 4; ++ks) {
            unsigned a[2][4], b[4][2];
#pragma unroll
            for (int mt = 0; mt < 2; ++mt) {
                uint32_t addr = aT + SWZ((uint32_t)((arow0 + mt * 16) * 128 + (ks * 2 + au) * 16));
                ldm_x4(a[mt][0], a[mt][1], a[mt][2], a[mt][3], addr);
            }
#pragma unroll
            for (int p = 0; p < 2; ++p) {
                uint32_t addr = bT + SWZ((uint32_t)((brow0 + p * 16) * 128 + (ks * 2 + bu) * 16));
                ldm_x4(b[2 * p][0], b[2 * p][1], b[2 * p + 1][0], b[2 * p + 1][1], addr);
            }
#pragma unroll
            for (int mt = 0; mt < 2; ++mt)
#pragma unroll
                for (int nt = 0; nt < 4; ++nt)
                    mma16h(c[mt][nt], a[mt], b[nt]);
        }
    }

#pragma unroll
    for (int mt = 0; mt < 2; ++mt) {
        int r0 = wm + mt * 16 + gr;
#pragma unroll
        for (int nt = 0; nt < 4; ++nt) {
            int c0 = wn + nt * 8 + 2 * q4;
            *(float2*)(Cb + (size_t)r0 * HW + c0) =
                make_float2(c[mt][nt][0] * UNSCALE, c[mt][nt][1] * UNSCALE);
            *(float2*)(Cb + (size_t)(r0 + 8) * HW + c0) =
                make_float2(c[mt][nt][2] * UNSCALE, c[mt][nt][3] * UNSCALE);
        }
    }
}

// ---------------- launch ----------------
extern "C" void kernel_launch(void* const* d_in, const int* in_sizes, int n_in,
                              void* d_out, int out_size) {
    const float* x  = (const float*)d_in[0];
    const float* Wq = (const float*)d_in[1];
    const float* Wk = (const float*)d_in[2];
    const float* Wv = (const float*)d_in[3];
    const float* Wo = (const float*)d_in[4];
    const float* gm = (const float*)d_in[5];
    float* out = (float*)d_out;

    float *wall, *qku, *gz;
    __half *uh, *ph;
    cudaGetSymbolAddress((void**)&wall, g_WallT);
    cudaGetSymbolAddress((void**)&qku,  g_QKU);
    cudaGetSymbolAddress((void**)&gz,   g_Z);
    cudaGetSymbolAddress((void**)&uh,   g_Uh);
    cudaGetSymbolAddress((void**)&ph,   g_Ph);

    // K0: combined weights (gamma folded into U-matrix) + zero z accumulators
    build_wall<<<MALL, 256>>>(Wq, Wk, Wv, Wo, gm);

    // K1: Q/K rows -> fp32 g_QKU (block x=0); U rows -> fp16*2^12 g_Uh (blocks x>0)
    gemm_tn<<<dim3(MALL / BM, HW / BN, NB), 256>>>(
        wall, MALL,
        x, (long long)CC * HW, HW,
        qku, (long long)MALL * HW, HW,
        uh, (long long)CC * HW,
        CC);

    // E': P^T = exp(K^T-rows x Q)  (fp16 mma), fp16 out, z column sums
    gemm_e<<<dim3(HW / BN, HW / BM, NB), 256>>>(
        qku + 32 * HW, (long long)MALL * HW, HW,    // A = K part
        qku,           (long long)MALL * HW, HW,    // B = Q part
        ph, (long long)HW * HW, HW,
        gz);

    // zscale: Uh *= 1/z  (fp16 in place)
    zscale<<<dim3(CC * HW / 512, NB), 256>>>();

    // K5 v7: fine-grained fp16 NT GEMM (128x64 tiles, f32 accum) — at HMMA issue floor
    cudaFuncSetAttribute(gemm_nt_f16_v7, cudaFuncAttributeMaxDynamicSharedMemorySize, K5_SMEM);
    gemm_nt_f16_v7<<<dim3(CC / K5_BM, HW / K5_BN, NB), 256, K5_SMEM>>>(uh, ph, out);
}